// round 9
// baseline (speedup 1.0000x reference)
#include <cuda_runtime.h>

#define NN 8192
#define EE 524288

// ---------------- scratch (device globals; 16B-aligned; no allocations) ----------------
__device__ __align__(16) float g_deg[NN];
__device__ __align__(16) float g_dinv[NN];
__device__ __align__(16) float g_h[NN * 4];   // per-node linear output (h = x @ W.T)
__device__ __align__(16) float g_a[NN * 4];   // conv1 aggregation (bias/relu deferred)
__device__ __align__(16) float g_b[NN * 4];   // conv2 aggregation (bias/relu deferred)
__device__ __align__(16) float g_x[NN];       // conv3 aggregation (bias folded into GEMV)
__device__ __align__(16) float g_y[2 * NN];   // hidden MLP activation

__device__ __forceinline__ float* buf(int id) {
    switch (id) {
        case 0:  return g_h;
        case 1:  return g_a;
        case 2:  return g_b;
        case 3:  return g_x;
        default: return g_y;
    }
}

// ---------------- setup ----------------
__global__ void k_zero_deg() {
    int i = blockIdx.x * blockDim.x + threadIdx.x;
    if (i < NN) g_deg[i] = 0.0f;   // self-loop's +1 folded into rsqrt later
}

__global__ void k_deg(const int* __restrict__ edge) {
    int e = blockIdx.x * blockDim.x + threadIdx.x;
    if (e < EE) atomicAdd(&g_deg[edge[EE + e]], 1.0f);
}

// ---------------- GCN conv pieces ----------------
// h[i] = act(in[i]) @ W.T ; out[i] = dinv[i]^2 * h[i]  (self-loop term)
// COMPUTE_DINV: first lin after k_deg — computes dinv[i] inline (kills a kernel).
// FUSE_PREV: act(v) = relu(v + pb[c]) — fuses previous conv's bias+relu epilogue.
template <int IC, int OC, bool FUSE_PREV, bool COMPUTE_DINV>
__global__ void k_lin(const float* __restrict__ in_ext, int in_id,
                      const float* __restrict__ pb,
                      const float* __restrict__ W, int out_id) {
    int i = blockIdx.x * blockDim.x + threadIdx.x;
    if (i >= NN) return;
    const float* in = (in_id < 0) ? in_ext : buf(in_id);
    float* h   = g_h;
    float* out = buf(out_id);
    float xi[IC];
#pragma unroll
    for (int c = 0; c < IC; c++) {
        float v = in[i * IC + c];
        if (FUSE_PREV) v = fmaxf(v + __ldg(&pb[c]), 0.f);
        xi[c] = v;
    }
    float dv;
    if (COMPUTE_DINV) {
        dv = rsqrtf(g_deg[i] + 1.0f);   // +1 = self-loop
        g_dinv[i] = dv;
    } else {
        dv = g_dinv[i];
    }
    float dv2 = dv * dv;
#pragma unroll
    for (int oc = 0; oc < OC; oc++) {
        float s = 0.f;
#pragma unroll
        for (int c = 0; c < IC; c++) s = fmaf(xi[c], __ldg(&W[oc * IC + c]), s);
        h[i * OC + oc] = s;
        out[i * OC + oc] = dv2 * s;
    }
}

// edge-parallel scatter; norm computed inline from L1/L2-resident dinv (no g_norm pass)
__global__ void k_scatter4(const int* __restrict__ edge, int out_id) {
    int e = blockIdx.x * blockDim.x + threadIdx.x;
    if (e >= EE) return;
    float* out = buf(out_id);
    int s = edge[e];
    int d = edge[EE + e];
    float nm = __ldg(&g_dinv[s]) * __ldg(&g_dinv[d]);
    float4 h = *reinterpret_cast<const float4*>(g_h + 4 * s);
    asm volatile("red.global.add.v4.f32 [%0], {%1, %2, %3, %4};"
                 :: "l"(out + 4 * d),
                    "f"(nm * h.x), "f"(nm * h.y), "f"(nm * h.z), "f"(nm * h.w)
                 : "memory");
}

__global__ void k_scatter2(const int* __restrict__ edge, int out_id) {
    int e = blockIdx.x * blockDim.x + threadIdx.x;
    if (e >= EE) return;
    float* out = buf(out_id);
    int s = edge[e];
    int d = edge[EE + e];
    float nm = __ldg(&g_dinv[s]) * __ldg(&g_dinv[d]);
    float2 h = *reinterpret_cast<const float2*>(g_h + 2 * s);
    asm volatile("red.global.add.v2.f32 [%0], {%1, %2};"
                 :: "l"(out + 2 * d), "f"(nm * h.x), "f"(nm * h.y)
                 : "memory");
}

__global__ void k_scatter1(const int* __restrict__ edge, int out_id) {
    int e = blockIdx.x * blockDim.x + threadIdx.x;
    if (e >= EE) return;
    float* out = buf(out_id);
    int s = edge[e];
    int d = edge[EE + e];
    float nm = __ldg(&g_dinv[s]) * __ldg(&g_dinv[d]);
    atomicAdd(&out[d], nm * g_h[s]);
}

// ---------------- big GEMV: y[row] = tanh(dot(W[row,:], x + xb) + b[row]) ----------------
// GR=8 rows per block (proven best), 512 threads for deeper MLP on the DRAM-bound W stream.
#define GR 8
#define GT 512
#define GW (GT / 32)
__global__ void __launch_bounds__(GT)
k_gemv_tanh_multi(const float* __restrict__ W, int x_id,
                  const float* __restrict__ xb,   // scalar bias folded into x (or null)
                  const float* __restrict__ b,
                  float* __restrict__ y_ext, int y_id,
                  int ncols) {
    const float* x = buf(x_id);
    float* y = (y_id < 0) ? y_ext : buf(y_id);
    int row0 = blockIdx.x * GR;
    int nc4 = ncols >> 2;
    float xbv = xb ? __ldg(&xb[0]) : 0.f;
    const float4* x4 = reinterpret_cast<const float4*>(x);

    float acc[GR];
#pragma unroll
    for (int r = 0; r < GR; r++) acc[r] = 0.f;

    for (int i = threadIdx.x; i < nc4; i += GT) {
        float4 c = __ldg(&x4[i]);
        c.x += xbv; c.y += xbv; c.z += xbv; c.w += xbv;
#pragma unroll
        for (int r = 0; r < GR; r++) {
            const float4* w4 = reinterpret_cast<const float4*>(W) + (size_t)(row0 + r) * nc4;
            float4 a = __ldcs(&w4[i]);
            acc[r] = fmaf(a.x, c.x, acc[r]);
            acc[r] = fmaf(a.y, c.y, acc[r]);
            acc[r] = fmaf(a.z, c.z, acc[r]);
            acc[r] = fmaf(a.w, c.w, acc[r]);
        }
    }

    int lane = threadIdx.x & 31;
    int w = threadIdx.x >> 5;
#pragma unroll
    for (int r = 0; r < GR; r++)
#pragma unroll
        for (int off = 16; off; off >>= 1)
            acc[r] += __shfl_down_sync(0xffffffffu, acc[r], off);

    __shared__ float part[GR][GW];
    if (lane == 0)
#pragma unroll
        for (int r = 0; r < GR; r++) part[r][w] = acc[r];
    __syncthreads();
    if (threadIdx.x < GR) {
        float s = 0.f;
#pragma unroll
        for (int ww = 0; ww < GW; ww++) s += part[threadIdx.x][ww];
        int row = row0 + threadIdx.x;
        y[row] = tanhf(s + __ldg(&b[row]));
    }
}

// small GEMV (final layer): one block per row
__global__ void k_gemv_tanh(const float* __restrict__ W, int x_id,
                            const float* __restrict__ b,
                            float* __restrict__ y_ext, int y_id,
                            int ncols) {
    int row = blockIdx.x;
    const float* x = buf(x_id);
    float* y = (y_id < 0) ? y_ext : buf(y_id);
    int nc4 = ncols >> 2;
    const float4* w4 = reinterpret_cast<const float4*>(W) + (size_t)row * nc4;
    const float4* x4 = reinterpret_cast<const float4*>(x);
    float s = 0.f;
    for (int i = threadIdx.x; i < nc4; i += blockDim.x) {
        float4 a = w4[i];
        float4 c = x4[i];
        s = fmaf(a.x, c.x, s);
        s = fmaf(a.y, c.y, s);
        s = fmaf(a.z, c.z, s);
        s = fmaf(a.w, c.w, s);
    }
#pragma unroll
    for (int off = 16; off; off >>= 1) s += __shfl_down_sync(0xffffffffu, s, off);
    __shared__ float ws[32];
    int lane = threadIdx.x & 31;
    int w = threadIdx.x >> 5;
    if (lane == 0) ws[w] = s;
    __syncthreads();
    if (w == 0) {
        int nw = blockDim.x >> 5;
        s = (lane < nw) ? ws[lane] : 0.f;
#pragma unroll
        for (int off = 16; off; off >>= 1) s += __shfl_down_sync(0xffffffffu, s, off);
        if (lane == 0) y[row] = tanhf(s + __ldg(&b[row]));
    }
}

// ---------------- launch ----------------
extern "C" void kernel_launch(void* const* d_in, const int* in_sizes, int n_in,
                              void* d_out, int out_size) {
    const float* data = (const float*)d_in[0];   // [N,2]
    const int*   edge = (const int*)d_in[1];     // [2,E] int32 (JAX x64 disabled)
    const float* W1 = (const float*)d_in[2];     // [4,2]
    const float* b1 = (const float*)d_in[3];     // [4]
    const float* W2 = (const float*)d_in[4];     // [2,4]
    const float* b2 = (const float*)d_in[5];     // [2]
    const float* W3 = (const float*)d_in[6];     // [1,2]
    const float* b3 = (const float*)d_in[7];     // [1]
    const float* Wa = (const float*)d_in[8];     // [2N, N]
    const float* ba = (const float*)d_in[9];     // [2N]
    const float* Wb = (const float*)d_in[10];    // [32, 2N]
    const float* bb = (const float*)d_in[11];    // [32]
    float* out = (float*)d_out;                  // [1, 32]

    // buffer ids: 0=g_h, 1=g_a, 2=g_b, 3=g_x, 4=g_y
    const int T = 256;
    const int GN = (NN + T - 1) / T;       // 32
    const int GE = (EE + T - 1) / T;       // 2048

    // degree (edge structure identical across all 3 convs)
    k_zero_deg<<<GN, T>>>();
    k_deg<<<GE, T>>>(edge);

    // conv1: [N,2] -> [N,4]   (computes dinv inline; bias+relu deferred into lin2)
    k_lin<2, 4, false, true><<<GN, T>>>(data, -1, nullptr, W1, 1);
    k_scatter4<<<GE, T>>>(edge, 1);

    // conv2: [N,4] -> [N,2]   (applies b1+relu on read; bias+relu deferred into lin3)
    k_lin<4, 2, true, false><<<GN, T>>>(nullptr, 1, b1, W2, 2);
    k_scatter2<<<GE, T>>>(edge, 2);

    // conv3: [N,2] -> [N,1]   (applies b2+relu on read; b3 folded into the GEMV x-read)
    k_lin<2, 1, true, false><<<GN, T>>>(nullptr, 2, b2, W3, 3);
    k_scatter1<<<GE, T>>>(edge, 3);

    // MLP: tanh((x+b3) @ Wa.T + ba) -> tanh(y @ Wb.T + bb)
    k_gemv_tanh_multi<<<2 * NN / GR, GT>>>(Wa, 3, b3, ba, nullptr, 4, NN);
    k_gemv_tanh<<<32, 256>>>(Wb, 4, bb, out, -1, 2 * NN);
}

// round 10
// speedup vs baseline: 1.1742x; 1.1742x over previous
#include <cuda_runtime.h>

#define NN 8192
#define EE 524288

// ---------------- scratch (device globals; 16B-aligned; no allocations) ----------------
__device__ __align__(16) float g_deg[NN];
__device__ __align__(16) float g_dinv[NN];
__device__ __align__(16) float g_norm[EE];
__device__ __align__(16) float g_h[NN * 4];   // per-node linear output (h = x @ W.T)
__device__ __align__(16) float g_a[NN * 4];   // conv1 aggregation (bias/relu deferred)
__device__ __align__(16) float g_b[NN * 4];   // conv2 aggregation (bias/relu deferred)
__device__ __align__(16) float g_x[NN];       // conv3 aggregation (bias folded into GEMV)
__device__ __align__(16) float g_y[2 * NN];   // hidden MLP activation

__device__ __forceinline__ float* buf(int id) {
    switch (id) {
        case 0:  return g_h;
        case 1:  return g_a;
        case 2:  return g_b;
        case 3:  return g_x;
        default: return g_y;
    }
}

// ---------------- setup ----------------
__global__ void k_init_deg() {
    int i = blockIdx.x * blockDim.x + threadIdx.x;
    if (i < NN) g_deg[i] = 1.0f;   // self-loop
}

// 4 edges per thread: int4 load of dst, 4 independent atomics (MLP up)
__global__ void k_deg(const int* __restrict__ edge) {
    int e4 = blockIdx.x * blockDim.x + threadIdx.x;
    if (e4 >= EE / 4) return;
    int4 d = reinterpret_cast<const int4*>(edge + EE)[e4];
    atomicAdd(&g_deg[d.x], 1.0f);
    atomicAdd(&g_deg[d.y], 1.0f);
    atomicAdd(&g_deg[d.z], 1.0f);
    atomicAdd(&g_deg[d.w], 1.0f);
}

__global__ void k_dinv() {
    int i = blockIdx.x * blockDim.x + threadIdx.x;
    if (i < NN) g_dinv[i] = rsqrtf(g_deg[i]);
}

// 4 edges per thread: batched index loads, 8 independent dinv gathers, float4 store
__global__ void k_norm(const int* __restrict__ edge) {
    int e4 = blockIdx.x * blockDim.x + threadIdx.x;
    if (e4 >= EE / 4) return;
    int4 s = reinterpret_cast<const int4*>(edge)[e4];
    int4 d = reinterpret_cast<const int4*>(edge + EE)[e4];
    float4 nm;
    nm.x = __ldg(&g_dinv[s.x]) * __ldg(&g_dinv[d.x]);
    nm.y = __ldg(&g_dinv[s.y]) * __ldg(&g_dinv[d.y]);
    nm.z = __ldg(&g_dinv[s.z]) * __ldg(&g_dinv[d.z]);
    nm.w = __ldg(&g_dinv[s.w]) * __ldg(&g_dinv[d.w]);
    reinterpret_cast<float4*>(g_norm)[e4] = nm;
}

// ---------------- GCN conv pieces ----------------
// h[i] = act(in[i]) @ W.T ; out[i] = dinv[i]^2 * h[i]  (self-loop term)
// FUSE_PREV: act(v) = relu(v + pb[c]) — fuses previous conv's bias+relu epilogue.
template <int IC, int OC, bool FUSE_PREV>
__global__ void k_lin(const float* __restrict__ in_ext, int in_id,
                      const float* __restrict__ pb,
                      const float* __restrict__ W, int out_id) {
    int i = blockIdx.x * blockDim.x + threadIdx.x;
    if (i >= NN) return;
    const float* in = (in_id < 0) ? in_ext : buf(in_id);
    float* h   = g_h;
    float* out = buf(out_id);
    float xi[IC];
#pragma unroll
    for (int c = 0; c < IC; c++) {
        float v = in[i * IC + c];
        if (FUSE_PREV) v = fmaxf(v + __ldg(&pb[c]), 0.f);
        xi[c] = v;
    }
    float dv = g_dinv[i];
    float dv2 = dv * dv;
#pragma unroll
    for (int oc = 0; oc < OC; oc++) {
        float s = 0.f;
#pragma unroll
        for (int c = 0; c < IC; c++) s = fmaf(xi[c], __ldg(&W[oc * IC + c]), s);
        h[i * OC + oc] = s;
        out[i * OC + oc] = dv2 * s;
    }
}

// edge-parallel scatters, 4 edges per thread, front-batched loads for MLP
__global__ void k_scatter4(const int* __restrict__ edge, int out_id) {
    int e4 = blockIdx.x * blockDim.x + threadIdx.x;
    if (e4 >= EE / 4) return;
    float* out = buf(out_id);
    int4 s = reinterpret_cast<const int4*>(edge)[e4];
    int4 d = reinterpret_cast<const int4*>(edge + EE)[e4];
    float4 nm = reinterpret_cast<const float4*>(g_norm)[e4];
    float4 h0 = *reinterpret_cast<const float4*>(g_h + 4 * s.x);
    float4 h1 = *reinterpret_cast<const float4*>(g_h + 4 * s.y);
    float4 h2 = *reinterpret_cast<const float4*>(g_h + 4 * s.z);
    float4 h3 = *reinterpret_cast<const float4*>(g_h + 4 * s.w);
    asm volatile("red.global.add.v4.f32 [%0], {%1, %2, %3, %4};"
                 :: "l"(out + 4 * d.x),
                    "f"(nm.x * h0.x), "f"(nm.x * h0.y), "f"(nm.x * h0.z), "f"(nm.x * h0.w)
                 : "memory");
    asm volatile("red.global.add.v4.f32 [%0], {%1, %2, %3, %4};"
                 :: "l"(out + 4 * d.y),
                    "f"(nm.y * h1.x), "f"(nm.y * h1.y), "f"(nm.y * h1.z), "f"(nm.y * h1.w)
                 : "memory");
    asm volatile("red.global.add.v4.f32 [%0], {%1, %2, %3, %4};"
                 :: "l"(out + 4 * d.z),
                    "f"(nm.z * h2.x), "f"(nm.z * h2.y), "f"(nm.z * h2.z), "f"(nm.z * h2.w)
                 : "memory");
    asm volatile("red.global.add.v4.f32 [%0], {%1, %2, %3, %4};"
                 :: "l"(out + 4 * d.w),
                    "f"(nm.w * h3.x), "f"(nm.w * h3.y), "f"(nm.w * h3.z), "f"(nm.w * h3.w)
                 : "memory");
}

__global__ void k_scatter2(const int* __restrict__ edge, int out_id) {
    int e4 = blockIdx.x * blockDim.x + threadIdx.x;
    if (e4 >= EE / 4) return;
    float* out = buf(out_id);
    int4 s = reinterpret_cast<const int4*>(edge)[e4];
    int4 d = reinterpret_cast<const int4*>(edge + EE)[e4];
    float4 nm = reinterpret_cast<const float4*>(g_norm)[e4];
    float2 h0 = *reinterpret_cast<const float2*>(g_h + 2 * s.x);
    float2 h1 = *reinterpret_cast<const float2*>(g_h + 2 * s.y);
    float2 h2 = *reinterpret_cast<const float2*>(g_h + 2 * s.z);
    float2 h3 = *reinterpret_cast<const float2*>(g_h + 2 * s.w);
    asm volatile("red.global.add.v2.f32 [%0], {%1, %2};"
                 :: "l"(out + 2 * d.x), "f"(nm.x * h0.x), "f"(nm.x * h0.y) : "memory");
    asm volatile("red.global.add.v2.f32 [%0], {%1, %2};"
                 :: "l"(out + 2 * d.y), "f"(nm.y * h1.x), "f"(nm.y * h1.y) : "memory");
    asm volatile("red.global.add.v2.f32 [%0], {%1, %2};"
                 :: "l"(out + 2 * d.z), "f"(nm.z * h2.x), "f"(nm.z * h2.y) : "memory");
    asm volatile("red.global.add.v2.f32 [%0], {%1, %2};"
                 :: "l"(out + 2 * d.w), "f"(nm.w * h3.x), "f"(nm.w * h3.y) : "memory");
}

__global__ void k_scatter1(const int* __restrict__ edge, int out_id) {
    int e4 = blockIdx.x * blockDim.x + threadIdx.x;
    if (e4 >= EE / 4) return;
    float* out = buf(out_id);
    int4 s = reinterpret_cast<const int4*>(edge)[e4];
    int4 d = reinterpret_cast<const int4*>(edge + EE)[e4];
    float4 nm = reinterpret_cast<const float4*>(g_norm)[e4];
    float h0 = g_h[s.x], h1 = g_h[s.y], h2 = g_h[s.z], h3 = g_h[s.w];
    atomicAdd(&out[d.x], nm.x * h0);
    atomicAdd(&out[d.y], nm.y * h1);
    atomicAdd(&out[d.z], nm.z * h2);
    atomicAdd(&out[d.w], nm.w * h3);
}

// ---------------- big GEMV (R7-proven config: GR=8, 256 threads) ----------------
#define GR 8
__global__ void k_gemv_tanh_multi(const float* __restrict__ W, int x_id,
                                  const float* __restrict__ xb,   // scalar bias folded into x (or null)
                                  const float* __restrict__ b,
                                  float* __restrict__ y_ext, int y_id,
                                  int ncols) {
    const float* x = buf(x_id);
    float* y = (y_id < 0) ? y_ext : buf(y_id);
    int row0 = blockIdx.x * GR;
    int nc4 = ncols >> 2;
    float xbv = xb ? __ldg(&xb[0]) : 0.f;
    const float4* x4 = reinterpret_cast<const float4*>(x);

    float acc[GR];
#pragma unroll
    for (int r = 0; r < GR; r++) acc[r] = 0.f;

    for (int i = threadIdx.x; i < nc4; i += blockDim.x) {
        float4 c = x4[i];
        c.x += xbv; c.y += xbv; c.z += xbv; c.w += xbv;
#pragma unroll
        for (int r = 0; r < GR; r++) {
            const float4* w4 = reinterpret_cast<const float4*>(W) + (size_t)(row0 + r) * nc4;
            float4 a = __ldcs(&w4[i]);
            acc[r] = fmaf(a.x, c.x, acc[r]);
            acc[r] = fmaf(a.y, c.y, acc[r]);
            acc[r] = fmaf(a.z, c.z, acc[r]);
            acc[r] = fmaf(a.w, c.w, acc[r]);
        }
    }

    int lane = threadIdx.x & 31;
    int w = threadIdx.x >> 5;
#pragma unroll
    for (int r = 0; r < GR; r++)
#pragma unroll
        for (int off = 16; off; off >>= 1)
            acc[r] += __shfl_down_sync(0xffffffffu, acc[r], off);

    __shared__ float part[GR][8];   // blockDim = 256 -> 8 warps
    if (lane == 0)
#pragma unroll
        for (int r = 0; r < GR; r++) part[r][w] = acc[r];
    __syncthreads();
    if (threadIdx.x < GR) {
        float s = 0.f;
#pragma unroll
        for (int ww = 0; ww < 8; ww++) s += part[threadIdx.x][ww];
        int row = row0 + threadIdx.x;
        y[row] = tanhf(s + __ldg(&b[row]));
    }
}

// small GEMV (final layer): one block per row
__global__ void k_gemv_tanh(const float* __restrict__ W, int x_id,
                            const float* __restrict__ b,
                            float* __restrict__ y_ext, int y_id,
                            int ncols) {
    int row = blockIdx.x;
    const float* x = buf(x_id);
    float* y = (y_id < 0) ? y_ext : buf(y_id);
    int nc4 = ncols >> 2;
    const float4* w4 = reinterpret_cast<const float4*>(W) + (size_t)row * nc4;
    const float4* x4 = reinterpret_cast<const float4*>(x);
    float s = 0.f;
    for (int i = threadIdx.x; i < nc4; i += blockDim.x) {
        float4 a = w4[i];
        float4 c = x4[i];
        s = fmaf(a.x, c.x, s);
        s = fmaf(a.y, c.y, s);
        s = fmaf(a.z, c.z, s);
        s = fmaf(a.w, c.w, s);
    }
#pragma unroll
    for (int off = 16; off; off >>= 1) s += __shfl_down_sync(0xffffffffu, s, off);
    __shared__ float ws[32];
    int lane = threadIdx.x & 31;
    int w = threadIdx.x >> 5;
    if (lane == 0) ws[w] = s;
    __syncthreads();
    if (w == 0) {
        int nw = blockDim.x >> 5;
        s = (lane < nw) ? ws[lane] : 0.f;
#pragma unroll
        for (int off = 16; off; off >>= 1) s += __shfl_down_sync(0xffffffffu, s, off);
        if (lane == 0) y[row] = tanhf(s + __ldg(&b[row]));
    }
}

// ---------------- launch ----------------
extern "C" void kernel_launch(void* const* d_in, const int* in_sizes, int n_in,
                              void* d_out, int out_size) {
    const float* data = (const float*)d_in[0];   // [N,2]
    const int*   edge = (const int*)d_in[1];     // [2,E] int32 (JAX x64 disabled)
    const float* W1 = (const float*)d_in[2];     // [4,2]
    const float* b1 = (const float*)d_in[3];     // [4]
    const float* W2 = (const float*)d_in[4];     // [2,4]
    const float* b2 = (const float*)d_in[5];     // [2]
    const float* W3 = (const float*)d_in[6];     // [1,2]
    const float* b3 = (const float*)d_in[7];     // [1]
    const float* Wa = (const float*)d_in[8];     // [2N, N]
    const float* ba = (const float*)d_in[9];     // [2N]
    const float* Wb = (const float*)d_in[10];    // [32, 2N]
    const float* bb = (const float*)d_in[11];    // [32]
    float* out = (float*)d_out;                  // [1, 32]

    // buffer ids: 0=g_h, 1=g_a, 2=g_b, 3=g_x, 4=g_y
    const int T = 256;
    const int GN  = (NN + T - 1) / T;          // 32
    const int GE4 = (EE / 4 + T - 1) / T;      // 512

    // degree / normalization (edge structure identical across all 3 convs)
    k_init_deg<<<GN, T>>>();
    k_deg<<<GE4, T>>>(edge);
    k_dinv<<<GN, T>>>();
    k_norm<<<GE4, T>>>(edge);

    // conv1: [N,2] -> [N,4]   (bias+relu deferred into lin2)
    k_lin<2, 4, false><<<GN, T>>>(data, -1, nullptr, W1, 1);
    k_scatter4<<<GE4, T>>>(edge, 1);

    // conv2: [N,4] -> [N,2]   (applies b1+relu on read; bias+relu deferred into lin3)
    k_lin<4, 2, true><<<GN, T>>>(nullptr, 1, b1, W2, 2);
    k_scatter2<<<GE4, T>>>(edge, 2);

    // conv3: [N,2] -> [N,1]   (applies b2+relu on read; b3 folded into the GEMV x-read)
    k_lin<2, 1, true><<<GN, T>>>(nullptr, 2, b2, W3, 3);
    k_scatter1<<<GE4, T>>>(edge, 3);

    // MLP: tanh((x+b3) @ Wa.T + ba) -> tanh(y @ Wb.T + bb)
    k_gemv_tanh_multi<<<2 * NN / GR, 256>>>(Wa, 3, b3, ba, nullptr, 4, NN);
    k_gemv_tanh<<<32, 256>>>(Wb, 4, bb, out, -1, 2 * NN);
}

// round 11
// speedup vs baseline: 1.1950x; 1.0177x over previous
#include <cuda_runtime.h>

#define NN 8192
#define EE 524288

// ---------------- scratch (device globals; 16B-aligned; no allocations) ----------------
__device__ __align__(16) float g_deg[NN];
__device__ __align__(16) float g_dinv[NN];
__device__ __align__(16) float g_norm[EE];
__device__ __align__(16) float g_h[NN * 4];   // per-node linear output (h = x @ W.T)
__device__ __align__(16) float g_a[NN * 4];   // conv1 aggregation (bias/relu deferred)
__device__ __align__(16) float g_b[NN * 4];   // conv2 aggregation (bias/relu deferred)
__device__ __align__(16) float g_x[NN];       // conv3 aggregation (bias folded into GEMV)
__device__ __align__(16) float g_y[2 * NN];   // hidden MLP activation

__device__ __forceinline__ float* buf(int id) {
    switch (id) {
        case 0:  return g_h;
        case 1:  return g_a;
        case 2:  return g_b;
        case 3:  return g_x;
        default: return g_y;
    }
}

// ---------------- setup ----------------
__global__ void k_init_deg() {   // vectorized: 8192 floats = 2048 float4
    int i = blockIdx.x * blockDim.x + threadIdx.x;
    if (i < NN / 4) reinterpret_cast<float4*>(g_deg)[i] = make_float4(1.f, 1.f, 1.f, 1.f);
}

// 4 edges per thread: int4 load of dst, 4 independent atomics
__global__ void k_deg(const int* __restrict__ edge) {
    int e4 = blockIdx.x * blockDim.x + threadIdx.x;
    if (e4 >= EE / 4) return;
    int4 d = reinterpret_cast<const int4*>(edge + EE)[e4];
    atomicAdd(&g_deg[d.x], 1.0f);
    atomicAdd(&g_deg[d.y], 1.0f);
    atomicAdd(&g_deg[d.z], 1.0f);
    atomicAdd(&g_deg[d.w], 1.0f);
}

// ---------------- GCN conv pieces ----------------
// h[i] = act(in[i]) @ W.T ; out[i] = dinv[i]^2 * h[i]  (self-loop term)
// COMPUTE_DINV: computes dinv[i]=rsqrtf(deg[i]) inline (kills the k_dinv node).
// FUSE_PREV: act(v) = relu(v + pb[c]) — fuses previous conv's bias+relu epilogue.
template <int IC, int OC, bool FUSE_PREV, bool COMPUTE_DINV>
__global__ void k_lin(const float* __restrict__ in_ext, int in_id,
                      const float* __restrict__ pb,
                      const float* __restrict__ W, int out_id) {
    int i = blockIdx.x * blockDim.x + threadIdx.x;
    if (i >= NN) return;
    const float* in = (in_id < 0) ? in_ext : buf(in_id);
    float* h   = g_h;
    float* out = buf(out_id);
    float xi[IC];
#pragma unroll
    for (int c = 0; c < IC; c++) {
        float v = in[i * IC + c];
        if (FUSE_PREV) v = fmaxf(v + __ldg(&pb[c]), 0.f);
        xi[c] = v;
    }
    float dv;
    if (COMPUTE_DINV) {
        dv = rsqrtf(g_deg[i]);   // deg includes the self-loop's +1
        g_dinv[i] = dv;
    } else {
        dv = g_dinv[i];
    }
    float dv2 = dv * dv;
#pragma unroll
    for (int oc = 0; oc < OC; oc++) {
        float s = 0.f;
#pragma unroll
        for (int c = 0; c < IC; c++) s = fmaf(xi[c], __ldg(&W[oc * IC + c]), s);
        h[i * OC + oc] = s;
        out[i * OC + oc] = dv2 * s;
    }
}

// First scatter also computes norm (dinv L1-resident) and materializes g_norm
// for the later scatters — kills the separate k_norm node.
__global__ void k_scatter4(const int* __restrict__ edge, int out_id) {
    int e4 = blockIdx.x * blockDim.x + threadIdx.x;
    if (e4 >= EE / 4) return;
    float* out = buf(out_id);
    int4 s = reinterpret_cast<const int4*>(edge)[e4];
    int4 d = reinterpret_cast<const int4*>(edge + EE)[e4];
    float4 nm;
    nm.x = __ldg(&g_dinv[s.x]) * __ldg(&g_dinv[d.x]);
    nm.y = __ldg(&g_dinv[s.y]) * __ldg(&g_dinv[d.y]);
    nm.z = __ldg(&g_dinv[s.z]) * __ldg(&g_dinv[d.z]);
    nm.w = __ldg(&g_dinv[s.w]) * __ldg(&g_dinv[d.w]);
    reinterpret_cast<float4*>(g_norm)[e4] = nm;
    float4 h0 = *reinterpret_cast<const float4*>(g_h + 4 * s.x);
    float4 h1 = *reinterpret_cast<const float4*>(g_h + 4 * s.y);
    float4 h2 = *reinterpret_cast<const float4*>(g_h + 4 * s.z);
    float4 h3 = *reinterpret_cast<const float4*>(g_h + 4 * s.w);
    asm volatile("red.global.add.v4.f32 [%0], {%1, %2, %3, %4};"
                 :: "l"(out + 4 * d.x),
                    "f"(nm.x * h0.x), "f"(nm.x * h0.y), "f"(nm.x * h0.z), "f"(nm.x * h0.w)
                 : "memory");
    asm volatile("red.global.add.v4.f32 [%0], {%1, %2, %3, %4};"
                 :: "l"(out + 4 * d.y),
                    "f"(nm.y * h1.x), "f"(nm.y * h1.y), "f"(nm.y * h1.z), "f"(nm.y * h1.w)
                 : "memory");
    asm volatile("red.global.add.v4.f32 [%0], {%1, %2, %3, %4};"
                 :: "l"(out + 4 * d.z),
                    "f"(nm.z * h2.x), "f"(nm.z * h2.y), "f"(nm.z * h2.z), "f"(nm.z * h2.w)
                 : "memory");
    asm volatile("red.global.add.v4.f32 [%0], {%1, %2, %3, %4};"
                 :: "l"(out + 4 * d.w),
                    "f"(nm.w * h3.x), "f"(nm.w * h3.y), "f"(nm.w * h3.z), "f"(nm.w * h3.w)
                 : "memory");
}

__global__ void k_scatter2(const int* __restrict__ edge, int out_id) {
    int e4 = blockIdx.x * blockDim.x + threadIdx.x;
    if (e4 >= EE / 4) return;
    float* out = buf(out_id);
    int4 s = reinterpret_cast<const int4*>(edge)[e4];
    int4 d = reinterpret_cast<const int4*>(edge + EE)[e4];
    float4 nm = reinterpret_cast<const float4*>(g_norm)[e4];
    float2 h0 = *reinterpret_cast<const float2*>(g_h + 2 * s.x);
    float2 h1 = *reinterpret_cast<const float2*>(g_h + 2 * s.y);
    float2 h2 = *reinterpret_cast<const float2*>(g_h + 2 * s.z);
    float2 h3 = *reinterpret_cast<const float2*>(g_h + 2 * s.w);
    asm volatile("red.global.add.v2.f32 [%0], {%1, %2};"
                 :: "l"(out + 2 * d.x), "f"(nm.x * h0.x), "f"(nm.x * h0.y) : "memory");
    asm volatile("red.global.add.v2.f32 [%0], {%1, %2};"
                 :: "l"(out + 2 * d.y), "f"(nm.y * h1.x), "f"(nm.y * h1.y) : "memory");
    asm volatile("red.global.add.v2.f32 [%0], {%1, %2};"
                 :: "l"(out + 2 * d.z), "f"(nm.z * h2.x), "f"(nm.z * h2.y) : "memory");
    asm volatile("red.global.add.v2.f32 [%0], {%1, %2};"
                 :: "l"(out + 2 * d.w), "f"(nm.w * h3.x), "f"(nm.w * h3.y) : "memory");
}

__global__ void k_scatter1(const int* __restrict__ edge, int out_id) {
    int e4 = blockIdx.x * blockDim.x + threadIdx.x;
    if (e4 >= EE / 4) return;
    float* out = buf(out_id);
    int4 s = reinterpret_cast<const int4*>(edge)[e4];
    int4 d = reinterpret_cast<const int4*>(edge + EE)[e4];
    float4 nm = reinterpret_cast<const float4*>(g_norm)[e4];
    float h0 = g_h[s.x], h1 = g_h[s.y], h2 = g_h[s.z], h3 = g_h[s.w];
    atomicAdd(&out[d.x], nm.x * h0);
    atomicAdd(&out[d.y], nm.y * h1);
    atomicAdd(&out[d.z], nm.z * h2);
    atomicAdd(&out[d.w], nm.w * h3);
}

// ---------------- big GEMV (FROZEN at R7-proven config: GR=8, 256 threads) ----------------
#define GR 8
__global__ void k_gemv_tanh_multi(const float* __restrict__ W, int x_id,
                                  const float* __restrict__ xb,   // scalar bias folded into x (or null)
                                  const float* __restrict__ b,
                                  float* __restrict__ y_ext, int y_id,
                                  int ncols) {
    const float* x = buf(x_id);
    float* y = (y_id < 0) ? y_ext : buf(y_id);
    int row0 = blockIdx.x * GR;
    int nc4 = ncols >> 2;
    float xbv = xb ? __ldg(&xb[0]) : 0.f;
    const float4* x4 = reinterpret_cast<const float4*>(x);

    float acc[GR];
#pragma unroll
    for (int r = 0; r < GR; r++) acc[r] = 0.f;

    for (int i = threadIdx.x; i < nc4; i += blockDim.x) {
        float4 c = x4[i];
        c.x += xbv; c.y += xbv; c.z += xbv; c.w += xbv;
#pragma unroll
        for (int r = 0; r < GR; r++) {
            const float4* w4 = reinterpret_cast<const float4*>(W) + (size_t)(row0 + r) * nc4;
            float4 a = __ldcs(&w4[i]);
            acc[r] = fmaf(a.x, c.x, acc[r]);
            acc[r] = fmaf(a.y, c.y, acc[r]);
            acc[r] = fmaf(a.z, c.z, acc[r]);
            acc[r] = fmaf(a.w, c.w, acc[r]);
        }
    }

    int lane = threadIdx.x & 31;
    int w = threadIdx.x >> 5;
#pragma unroll
    for (int r = 0; r < GR; r++)
#pragma unroll
        for (int off = 16; off; off >>= 1)
            acc[r] += __shfl_down_sync(0xffffffffu, acc[r], off);

    __shared__ float part[GR][8];   // blockDim = 256 -> 8 warps
    if (lane == 0)
#pragma unroll
        for (int r = 0; r < GR; r++) part[r][w] = acc[r];
    __syncthreads();
    if (threadIdx.x < GR) {
        float s = 0.f;
#pragma unroll
        for (int ww = 0; ww < 8; ww++) s += part[threadIdx.x][ww];
        int row = row0 + threadIdx.x;
        y[row] = tanhf(s + __ldg(&b[row]));
    }
}

// small GEMV (final layer): one block per row
__global__ void k_gemv_tanh(const float* __restrict__ W, int x_id,
                            const float* __restrict__ b,
                            float* __restrict__ y_ext, int y_id,
                            int ncols) {
    int row = blockIdx.x;
    const float* x = buf(x_id);
    float* y = (y_id < 0) ? y_ext : buf(y_id);
    int nc4 = ncols >> 2;
    const float4* w4 = reinterpret_cast<const float4*>(W) + (size_t)row * nc4;
    const float4* x4 = reinterpret_cast<const float4*>(x);
    float s = 0.f;
    for (int i = threadIdx.x; i < nc4; i += blockDim.x) {
        float4 a = w4[i];
        float4 c = x4[i];
        s = fmaf(a.x, c.x, s);
        s = fmaf(a.y, c.y, s);
        s = fmaf(a.z, c.z, s);
        s = fmaf(a.w, c.w, s);
    }
#pragma unroll
    for (int off = 16; off; off >>= 1) s += __shfl_down_sync(0xffffffffu, s, off);
    __shared__ float ws[32];
    int lane = threadIdx.x & 31;
    int w = threadIdx.x >> 5;
    if (lane == 0) ws[w] = s;
    __syncthreads();
    if (w == 0) {
        int nw = blockDim.x >> 5;
        s = (lane < nw) ? ws[lane] : 0.f;
#pragma unroll
        for (int off = 16; off; off >>= 1) s += __shfl_down_sync(0xffffffffu, s, off);
        if (lane == 0) y[row] = tanhf(s + __ldg(&b[row]));
    }
}

// ---------------- launch ----------------
extern "C" void kernel_launch(void* const* d_in, const int* in_sizes, int n_in,
                              void* d_out, int out_size) {
    const float* data = (const float*)d_in[0];   // [N,2]
    const int*   edge = (const int*)d_in[1];     // [2,E] int32 (JAX x64 disabled)
    const float* W1 = (const float*)d_in[2];     // [4,2]
    const float* b1 = (const float*)d_in[3];     // [4]
    const float* W2 = (const float*)d_in[4];     // [2,4]
    const float* b2 = (const float*)d_in[5];     // [2]
    const float* W3 = (const float*)d_in[6];     // [1,2]
    const float* b3 = (const float*)d_in[7];     // [1]
    const float* Wa = (const float*)d_in[8];     // [2N, N]
    const float* ba = (const float*)d_in[9];     // [2N]
    const float* Wb = (const float*)d_in[10];    // [32, 2N]
    const float* bb = (const float*)d_in[11];    // [32]
    float* out = (float*)d_out;                  // [1, 32]

    // buffer ids: 0=g_h, 1=g_a, 2=g_b, 3=g_x, 4=g_y
    const int T = 256;
    const int GN  = (NN + T - 1) / T;          // 32
    const int GE4 = (EE / 4 + T - 1) / T;      // 512

    // degree (edge structure identical across all 3 convs)
    k_init_deg<<<(NN / 4 + T - 1) / T, T>>>();
    k_deg<<<GE4, T>>>(edge);

    // conv1: [N,2] -> [N,4]   (computes dinv inline; bias+relu deferred into lin2;
    //                          scatter4 computes+stores norm — no k_dinv/k_norm nodes)
    k_lin<2, 4, false, true><<<GN, T>>>(data, -1, nullptr, W1, 1);
    k_scatter4<<<GE4, T>>>(edge, 1);

    // conv2: [N,4] -> [N,2]   (applies b1+relu on read; bias+relu deferred into lin3)
    k_lin<4, 2, true, false><<<GN, T>>>(nullptr, 1, b1, W2, 2);
    k_scatter2<<<GE4, T>>>(edge, 2);

    // conv3: [N,2] -> [N,1]   (applies b2+relu on read; b3 folded into the GEMV x-read)
    k_lin<2, 1, true, false><<<GN, T>>>(nullptr, 2, b2, W3, 3);
    k_scatter1<<<GE4, T>>>(edge, 3);

    // MLP: tanh((x+b3) @ Wa.T + ba) -> tanh(y @ Wb.T + bb)
    k_gemv_tanh_multi<<<2 * NN / GR, 256>>>(Wa, 3, b3, ba, nullptr, 4, NN);
    k_gemv_tanh<<<32, 256>>>(Wb, 4, bb, out, -1, 2 * NN);
}